// round 4
// baseline (speedup 1.0000x reference)
#include <cuda_runtime.h>
#include <math.h>

#define NS 64          // coarse samples
#define NF 128         // fine samples
#define NC 192         // combined
#define WPB 8          // warps per block
#define FULL 0xffffffffu

// #{k in [0,128) : u_k < x}, u_k = 0.05 + k * (0.9/127)
__device__ __forceinline__ int count_u(float x) {
    int c = __float2int_ru((x - 0.05f) * (127.0f / 0.9f));
    return min(max(c, 0), NF);
}

__device__ __forceinline__ unsigned long long pack2(float lo, float hi) {
    unsigned long long r;
    asm("mov.b64 %0, {%1, %2};" : "=l"(r) : "f"(lo), "f"(hi));
    return r;
}
__device__ __forceinline__ void unpack2(unsigned long long v, float& lo, float& hi) {
    asm("mov.b64 {%0, %1}, %2;" : "=f"(lo), "=f"(hi) : "l"(v));
}
__device__ __forceinline__ unsigned long long addp(unsigned long long a, unsigned long long b) {
    unsigned long long r;
    asm("add.rn.f32x2 %0, %1, %2;" : "=l"(r) : "l"(a), "l"(b));
    return r;
}

__global__ __launch_bounds__(WPB * 32)
void pdf_sampler_kernel(const float* __restrict__ near_, const float* __restrict__ far_,
                        const float* __restrict__ density, const float* __restrict__ rgb,
                        float* __restrict__ zs_out, float* __restrict__ rgb_out,
                        float* __restrict__ depth_out, float* __restrict__ acc_out,
                        int B)
{
    __shared__ __align__(16) float s_z[WPB][NC];

    const int warp = threadIdx.x >> 5;
    const int lane = threadIdx.x & 31;
    const int ray  = blockIdx.x * WPB + warp;
    if (ray >= B) return;

    const float nr = near_[ray];
    const float fr = far_[ray];
    const float delta = (fr - nr) * (1.0f / NS);

    // ---- density: 2 elems per lane, coalesced float2 ----
    const float2 dv = *reinterpret_cast<const float2*>(density + (size_t)ray * NS + 2 * lane);
    const float e0 = dv.x * delta;
    const float e1 = dv.y * delta;

    // ---- warp inclusive prefix sum of optical depth (pair per lane) ----
    const float ps = e0 + e1;
    float s = ps;
    #pragma unroll
    for (int off = 1; off < 32; off <<= 1) {
        float v = __shfl_up_sync(FULL, s, off);
        if (lane >= off) s += v;
    }
    const float excl = s - ps;           // cum optical depth before elem 2*lane
    const float c0 = excl + e0;          // inclusive at 2*lane
    const float c1 = excl + ps;          // inclusive at 2*lane+1

    // weights: w_i = T_i * (1 - exp(-x_i))
    const float T0 = __expf(-excl);
    const float w0 = T0 * (1.0f - __expf(-e0));
    const float Tm = T0 - w0;            // = T0 * exp(-e0)
    const float w1 = Tm * (1.0f - __expf(-e1));

    // analytic mids
    const float m0 = fmaf((float)(2 * lane) + 0.5f, delta, nr);
    const float m1 = m0 + delta;

    // ---- rgb loads (6 contiguous floats per lane, coalesced) ----
    const float* rrow = rgb + (size_t)ray * (NS * 3) + 6 * lane;
    const float2 ra = *reinterpret_cast<const float2*>(rrow + 0);
    const float2 rb = *reinterpret_cast<const float2*>(rrow + 2);
    const float2 rc = *reinterpret_cast<const float2*>(rrow + 4);

    // ---- reductions (packed f32x2 butterflies): (rs,gs) and (bs,dsum) ----
    unsigned long long p0 = pack2(w0 * ra.x + w1 * rb.y,   // rs
                                  w0 * ra.y + w1 * rc.x);  // gs
    unsigned long long p1 = pack2(w0 * rb.x + w1 * rc.y,   // bs
                                  w0 * m0   + w1 * m1);    // dsum
    #pragma unroll
    for (int off = 16; off >= 1; off >>= 1) {
        p0 = addp(p0, __shfl_xor_sync(FULL, p0, off));
        p1 = addp(p1, __shfl_xor_sync(FULL, p1, off));
    }

    // total weight analytically from full optical depth (lane 31's c1)
    const float ctot = __shfl_sync(FULL, c1, 31);
    const float wsum = 1.0f - __expf(-ctot);
    const float inv  = __fdividef(1.0f, wsum + 1e-6f);

    // normalized cdf at this lane's two positions (registers only)
    const float cd0 = (1.0f - __expf(-c0)) * inv;
    const float cd1 = (1.0f - __expf(-c1)) * inv;
    float cprev = __shfl_up_sync(FULL, cd1, 1);     // cdf[2*lane - 1]
    if (lane == 0) cprev = 0.0f;

    // u-count boundaries for this lane's two intervals
    const int kS = count_u(cprev);   // first fine idx with pos >= 2*lane
    const int kM = count_u(cd0);     // first fine idx with pos >= 2*lane+1
    const int kE = count_u(cd1);     // first fine idx with pos >= 2*lane+2

    float* zw = s_z[warp];
    const int i0 = 2 * lane;
    const int i1 = i0 + 1;

    // ---- mids: rank = i + (# fine samples strictly before mid i) ----
    zw[(i0 == 0) ? 0 : (i0 + kM)] = m0;
    zw[i1 + kE] = m1;

    const float ustep = 0.9f / 127.0f;

    // ---- fused scatter loop over both intervals (affine z in k) ----
    {
        // interval A = p=i0 : k in [kS, kM)
        const float mbA = (i0 == 0) ? m0 : (m0 - delta);
        const float dmA = m0 - mbA;                    // 0 when i0==0
        const float dA  = cd0 - cprev;
        const float rdA = (dA < 1e-5f) ? 1.0f : __fdividef(1.0f, dA);
        const float gA  = rdA * dmA;
        float z  = fmaf(fmaf((float)kS, ustep, 0.05f) - cprev, gA, mbA);
        float dz = ustep * gA;
        float* wp = zw + kS + ((i0 == 0) ? 1 : i0);    // slot offset clamp(p,1,64)

        // interval B = p=i1 : k in [kM, kE)
        const float dB  = cd1 - cd0;
        const float rdB = (dB < 1e-5f) ? 1.0f : __fdividef(1.0f, dB);
        const float gB  = rdB * delta;
        const float zB  = fmaf(fmaf((float)kM, ustep, 0.05f) - cd0, gB, m0);
        const float dzB = ustep * gB;

        for (int k = kS; k < kE; ++k) {
            if (k == kM) { z = zB; dz = dzB; wp = zw + kM + i1; }
            *wp++ = z;
            z += dz;
        }
    }
    // ---- tail p = 64 (u >= cdf[63]): fz = mids[63], rank count = 64 ----
    if (lane == 31) {
        for (int k = kE; k < NF; ++k) zw[k + NS] = m1;
    }
    __syncwarp();

    // ---- TMA bulk store: smem row -> gmem (no LDS/STG readback) ----
    if (lane == 0) {
        asm volatile("fence.proxy.async.shared::cta;" ::: "memory");
        unsigned int saddr = (unsigned int)__cvta_generic_to_shared(zw);
        float* gdst = zs_out + (size_t)ray * NC;
        asm volatile("cp.async.bulk.global.shared::cta.bulk_group [%0], [%1], %2;"
                     :: "l"(gdst), "r"(saddr), "r"(NC * 4) : "memory");
        asm volatile("cp.async.bulk.commit_group;" ::: "memory");

        // scalar outputs
        float rs, gs, bs, dsum;
        unpack2(p0, rs, gs);
        unpack2(p1, bs, dsum);
        rgb_out[(size_t)ray * 3 + 0] = rs;
        rgb_out[(size_t)ray * 3 + 1] = gs;
        rgb_out[(size_t)ray * 3 + 2] = bs;
        depth_out[ray] = __fdividef(dsum, wsum + 1e-8f);
        acc_out[ray]   = wsum;

        // ensure the bulk store has fully completed before exit
        asm volatile("cp.async.bulk.wait_group 0;" ::: "memory");
    }
}

extern "C" void kernel_launch(void* const* d_in, const int* in_sizes, int n_in,
                              void* d_out, int out_size)
{
    const float* near_   = (const float*)d_in[0];
    const float* far_    = (const float*)d_in[1];
    const float* density = (const float*)d_in[2];
    const float* rgb     = (const float*)d_in[3];
    const int B = in_sizes[0];

    float* out   = (float*)d_out;
    float* zs    = out;                       // B * 192
    float* rgbo  = zs + (size_t)B * NC;       // B * 3
    float* depth = rgbo + (size_t)B * 3;      // B
    float* acc   = depth + B;                 // B

    const int blocks = (B + WPB - 1) / WPB;
    pdf_sampler_kernel<<<blocks, WPB * 32>>>(near_, far_, density, rgb,
                                             zs, rgbo, depth, acc, B);
}

// round 6
// speedup vs baseline: 1.6018x; 1.6018x over previous
#include <cuda_runtime.h>
#include <math.h>

#define NS 64          // coarse samples
#define NF 128         // fine samples
#define NC 192         // combined
#define WPB 8          // warps per block
#define FULL 0xffffffffu

// #{k in [0,128) : u_k < x}, u_k = 0.05 + k * (0.9/127)
__device__ __forceinline__ int count_u(float x) {
    int c = __float2int_ru((x - 0.05f) * (127.0f / 0.9f));
    return min(max(c, 0), NF);
}

__device__ __forceinline__ unsigned long long pack2(float lo, float hi) {
    unsigned long long r;
    asm("mov.b64 %0, {%1, %2};" : "=l"(r) : "f"(lo), "f"(hi));
    return r;
}
__device__ __forceinline__ void unpack2(unsigned long long v, float& lo, float& hi) {
    asm("mov.b64 {%0, %1}, %2;" : "=f"(lo), "=f"(hi) : "l"(v));
}
__device__ __forceinline__ unsigned long long addp(unsigned long long a, unsigned long long b) {
    unsigned long long r;
    asm("add.rn.f32x2 %0, %1, %2;" : "=l"(r) : "l"(a), "l"(b));
    return r;
}

__global__ __launch_bounds__(WPB * 32)
void pdf_sampler_kernel(const float* __restrict__ near_, const float* __restrict__ far_,
                        const float* __restrict__ density, const float* __restrict__ rgb,
                        float* __restrict__ zs_out, float* __restrict__ rgb_out,
                        float* __restrict__ depth_out, float* __restrict__ acc_out,
                        int B)
{
    __shared__ __align__(16) float s_z[WPB][NC];

    const int warp = threadIdx.x >> 5;
    const int lane = threadIdx.x & 31;
    const int ray  = blockIdx.x * WPB + warp;
    if (ray >= B) return;

    const float nr = near_[ray];
    const float fr = far_[ray];
    const float delta = (fr - nr) * (1.0f / NS);

    // ---- density: 2 elems per lane, coalesced float2 ----
    const float2 dv = *reinterpret_cast<const float2*>(density + (size_t)ray * NS + 2 * lane);
    const float e0 = dv.x * delta;
    const float e1 = dv.y * delta;

    // ---- warp inclusive prefix sum of optical depth (pair per lane) ----
    const float ps = e0 + e1;
    float s = ps;
    #pragma unroll
    for (int off = 1; off < 32; off <<= 1) {
        float v = __shfl_up_sync(FULL, s, off);
        if (lane >= off) s += v;
    }
    const float excl = s - ps;           // cum optical depth before elem 2*lane
    const float c0 = excl + e0;          // inclusive at 2*lane
    const float c1 = excl + ps;          // inclusive at 2*lane+1

    // weights: w_i = T_i * (1 - exp(-x_i))
    const float T0 = __expf(-excl);
    const float w0 = T0 * (1.0f - __expf(-e0));
    const float Tm = T0 - w0;            // = T0 * exp(-e0)
    const float w1 = Tm * (1.0f - __expf(-e1));

    // analytic mids
    const float m0 = fmaf((float)(2 * lane) + 0.5f, delta, nr);
    const float m1 = m0 + delta;

    // ---- rgb loads (6 contiguous floats per lane, coalesced) ----
    const float* rrow = rgb + (size_t)ray * (NS * 3) + 6 * lane;
    const float2 ra = *reinterpret_cast<const float2*>(rrow + 0);
    const float2 rb = *reinterpret_cast<const float2*>(rrow + 2);
    const float2 rc = *reinterpret_cast<const float2*>(rrow + 4);

    // ---- reductions (packed f32x2 butterflies): (rs,gs) and (bs,dsum) ----
    unsigned long long p0 = pack2(w0 * ra.x + w1 * rb.y,   // rs
                                  w0 * ra.y + w1 * rc.x);  // gs
    unsigned long long p1 = pack2(w0 * rb.x + w1 * rc.y,   // bs
                                  w0 * m0   + w1 * m1);    // dsum
    #pragma unroll
    for (int off = 16; off >= 1; off >>= 1) {
        p0 = addp(p0, __shfl_xor_sync(FULL, p0, off));
        p1 = addp(p1, __shfl_xor_sync(FULL, p1, off));
    }

    // total weight analytically from full optical depth (lane 31's c1)
    const float ctot = __shfl_sync(FULL, c1, 31);
    const float wsum = 1.0f - __expf(-ctot);
    const float inv  = __fdividef(1.0f, wsum + 1e-6f);

    // normalized cdf at this lane's two positions (registers only)
    const float cd0 = (1.0f - __expf(-c0)) * inv;
    const float cd1 = (1.0f - __expf(-c1)) * inv;
    float cprev = __shfl_up_sync(FULL, cd1, 1);     // cdf[2*lane - 1]
    if (lane == 0) cprev = 0.0f;

    // u-count boundaries for this lane's two intervals
    const int kS = count_u(cprev);   // first fine idx with pos >= 2*lane
    const int kM = count_u(cd0);     // first fine idx with pos >= 2*lane+1
    const int kE = count_u(cd1);     // first fine idx with pos >= 2*lane+2

    float* zw = s_z[warp];
    const int i0 = 2 * lane;
    const int i1 = i0 + 1;

    // ---- mids: rank = i + (# fine samples strictly before mid i) ----
    zw[(i0 == 0) ? 0 : (i0 + kM)] = m0;
    zw[i1 + kE] = m1;

    const float ustep = 0.9f / 127.0f;

    // ---- fused scatter loop over both intervals (affine z in k) ----
    {
        // interval A = p=i0 : k in [kS, kM)
        const float mbA = (i0 == 0) ? m0 : (m0 - delta);
        const float dmA = m0 - mbA;                    // 0 when i0==0
        const float dA  = cd0 - cprev;
        const float rdA = (dA < 1e-5f) ? 1.0f : __fdividef(1.0f, dA);
        const float gA  = rdA * dmA;
        float z  = fmaf(fmaf((float)kS, ustep, 0.05f) - cprev, gA, mbA);
        float dz = ustep * gA;
        float* wp = zw + kS + ((i0 == 0) ? 1 : i0);    // slot offset clamp(p,1,64)

        // interval B = p=i1 : k in [kM, kE)
        const float dB  = cd1 - cd0;
        const float rdB = (dB < 1e-5f) ? 1.0f : __fdividef(1.0f, dB);
        const float gB  = rdB * delta;
        const float zB  = fmaf(fmaf((float)kM, ustep, 0.05f) - cd0, gB, m0);
        const float dzB = ustep * gB;

        for (int k = kS; k < kE; ++k) {
            if (k == kM) { z = zB; dz = dzB; wp = zw + kM + i1; }
            *wp++ = z;
            z += dz;
        }
    }
    // ---- tail p = 64 (u >= cdf[63]): fz = mids[63], rank count = 64 ----
    if (lane == 31) {
        for (int k = kE; k < NF; ++k) zw[k + NS] = m1;
    }
    __syncwarp();

    // ---- coalesced vectorized write of the merged row ----
    float4* zv = reinterpret_cast<float4*>(zs_out + (size_t)ray * NC);
    const float4* sv = reinterpret_cast<const float4*>(zw);
    zv[lane] = sv[lane];                             // 32 float4 = 128 floats
    if (lane < 16) zv[32 + lane] = sv[32 + lane];    // remaining 64 floats

    // ---- scalar outputs, distributed (all lanes hold the reduced values) ----
    if (lane < 5) {
        float rs, gs, bs, dsum;
        unpack2(p0, rs, gs);
        unpack2(p1, bs, dsum);
        if (lane < 3) {
            const float v = (lane == 0) ? rs : (lane == 1) ? gs : bs;
            rgb_out[(size_t)ray * 3 + lane] = v;
        } else if (lane == 3) {
            depth_out[ray] = __fdividef(dsum, wsum + 1e-8f);
        } else {
            acc_out[ray] = wsum;
        }
    }
}

extern "C" void kernel_launch(void* const* d_in, const int* in_sizes, int n_in,
                              void* d_out, int out_size)
{
    const float* near_   = (const float*)d_in[0];
    const float* far_    = (const float*)d_in[1];
    const float* density = (const float*)d_in[2];
    const float* rgb     = (const float*)d_in[3];
    const int B = in_sizes[0];

    float* out   = (float*)d_out;
    float* zs    = out;                       // B * 192
    float* rgbo  = zs + (size_t)B * NC;       // B * 3
    float* depth = rgbo + (size_t)B * 3;      // B
    float* acc   = depth + B;                 // B

    const int blocks = (B + WPB - 1) / WPB;
    pdf_sampler_kernel<<<blocks, WPB * 32>>>(near_, far_, density, rgb,
                                             zs, rgbo, depth, acc, B);
}

// round 7
// speedup vs baseline: 2.2116x; 1.3807x over previous
#include <cuda_runtime.h>
#include <math.h>

#define NS 64          // coarse samples
#define NF 128         // fine samples
#define NC 192         // combined
#define WPB 8          // warps per block
#define FULL 0xffffffffu

// #{k in [0,128) : u_k < x}, u_k = 0.05 + k * (0.9/127)
__device__ __forceinline__ int count_u(float x) {
    int c = __float2int_ru((x - 0.05f) * (127.0f / 0.9f));
    return min(max(c, 0), NF);
}

__device__ __forceinline__ unsigned long long pack2(float lo, float hi) {
    unsigned long long r;
    asm("mov.b64 %0, {%1, %2};" : "=l"(r) : "f"(lo), "f"(hi));
    return r;
}
__device__ __forceinline__ void unpack2(unsigned long long v, float& lo, float& hi) {
    asm("mov.b64 {%0, %1}, %2;" : "=f"(lo), "=f"(hi) : "l"(v));
}
__device__ __forceinline__ unsigned long long addp(unsigned long long a, unsigned long long b) {
    unsigned long long r;
    asm("add.rn.f32x2 %0, %1, %2;" : "=l"(r) : "l"(a), "l"(b));
    return r;
}

__global__ __launch_bounds__(WPB * 32)
void pdf_sampler_kernel(const float* __restrict__ near_, const float* __restrict__ far_,
                        const float* __restrict__ density, const float* __restrict__ rgb,
                        float* __restrict__ zs_out, float* __restrict__ rgb_out,
                        float* __restrict__ depth_out, float* __restrict__ acc_out,
                        int B)
{
    __shared__ __align__(16) float s_z[WPB][NC];

    const int warp = threadIdx.x >> 5;
    const int lane = threadIdx.x & 31;
    const int ray  = blockIdx.x * WPB + warp;
    if (ray >= B) return;

    const float nr = near_[ray];
    const float fr = far_[ray];
    const float delta = (fr - nr) * (1.0f / NS);

    // ---- density: 2 elems per lane, coalesced float2 ----
    const float2 dv = *reinterpret_cast<const float2*>(density + (size_t)ray * NS + 2 * lane);
    const float e0 = dv.x * delta;
    const float e1 = dv.y * delta;

    // ---- warp inclusive prefix sum of optical depth (pair per lane) ----
    const float ps = e0 + e1;
    float s = ps;
    #pragma unroll
    for (int off = 1; off < 32; off <<= 1) {
        float v = __shfl_up_sync(FULL, s, off);
        if (lane >= off) s += v;
    }
    const float excl = s - ps;           // cum optical depth before elem 2*lane

    // weights: w_i = T_i * (1 - exp(-x_i)); only 3 exps needed, rest by identity
    const float T0 = __expf(-excl);              // exp(-cum before 2*lane)
    const float w0 = T0 * (1.0f - __expf(-e0));
    const float Tm = T0 - w0;                    // = exp(-c0)
    const float w1 = Tm * (1.0f - __expf(-e1));
    const float Te = Tm - w1;                    // = exp(-c1)

    // analytic mids
    const float m0 = fmaf((float)(2 * lane) + 0.5f, delta, nr);
    const float m1 = m0 + delta;

    // ---- rgb loads (6 contiguous floats per lane, coalesced) ----
    const float* rrow = rgb + (size_t)ray * (NS * 3) + 6 * lane;
    const float2 ra = *reinterpret_cast<const float2*>(rrow + 0);
    const float2 rb = *reinterpret_cast<const float2*>(rrow + 2);
    const float2 rc = *reinterpret_cast<const float2*>(rrow + 4);

    // ---- reductions (packed f32x2 butterflies): (rs,gs) and (bs,dsum) ----
    unsigned long long p0 = pack2(w0 * ra.x + w1 * rb.y,   // rs
                                  w0 * ra.y + w1 * rc.x);  // gs
    unsigned long long p1 = pack2(w0 * rb.x + w1 * rc.y,   // bs
                                  w0 * m0   + w1 * m1);    // dsum
    #pragma unroll
    for (int off = 16; off >= 1; off >>= 1) {
        p0 = addp(p0, __shfl_xor_sync(FULL, p0, off));
        p1 = addp(p1, __shfl_xor_sync(FULL, p1, off));
    }

    // total weight: exp(-ctot) is lane 31's Te
    const float wsum = 1.0f - __shfl_sync(FULL, Te, 31);
    const float inv  = __fdividef(1.0f, wsum + 1e-6f);

    // normalized cdf at this lane's two positions (registers only)
    const float cd0 = (1.0f - Tm) * inv;
    const float cd1 = (1.0f - Te) * inv;
    float cprev = __shfl_up_sync(FULL, cd1, 1);     // cdf[2*lane - 1]
    if (lane == 0) cprev = 0.0f;

    // u-count boundaries for this lane's two intervals
    const int kS = count_u(cprev);   // first fine idx with pos >= 2*lane
    const int kM = count_u(cd0);     // first fine idx with pos >= 2*lane+1
    const int kE = count_u(cd1);     // first fine idx with pos >= 2*lane+2

    float* zw = s_z[warp];
    const int i0 = 2 * lane;
    const int i1 = i0 + 1;

    // ---- mids: rank = i + (# fine samples strictly before mid i) ----
    zw[(i0 == 0) ? 0 : (i0 + kM)] = m0;
    zw[i1 + kE] = m1;

    const float ustep = 0.9f / 127.0f;

    // ---- interval p = i0 : fine k in [kS, kM); z affine in k ----
    {
        const float cb = cprev;
        const float mb = (i0 == 0) ? m0 : (m0 - delta);
        const float dm = m0 - mb;                    // 0 when i0==0 -> fz = m0
        const float d  = cd0 - cb;
        const float rd = (d < 1e-5f) ? 1.0f : __fdividef(1.0f, d);
        const float g  = rd * dm;
        float z        = fmaf(fmaf((float)kS, ustep, 0.05f) - cb, g, mb);
        const float dz = ustep * g;
        const int slotoff = (i0 == 0) ? 1 : i0;      // clamp(p,1,64)
        for (int k = kS; k < kM; ++k) { zw[k + slotoff] = z; z += dz; }
    }
    // ---- interval p = i1 : fine k in [kM, kE) ----
    {
        const float d  = cd1 - cd0;
        const float rd = (d < 1e-5f) ? 1.0f : __fdividef(1.0f, d);
        const float g  = rd * delta;
        float z        = fmaf(fmaf((float)kM, ustep, 0.05f) - cd0, g, m0);
        const float dz = ustep * g;
        for (int k = kM; k < kE; ++k) { zw[k + i1] = z; z += dz; }
    }
    // ---- tail p = 64 (u >= cdf[63]): fz = mids[63], rank count = 64 ----
    if (lane == 31) {
        for (int k = kE; k < NF; ++k) zw[k + NS] = m1;
    }
    __syncwarp();

    // ---- coalesced vectorized write of the merged row ----
    float4* zv = reinterpret_cast<float4*>(zs_out + (size_t)ray * NC);
    const float4* sv = reinterpret_cast<const float4*>(zw);
    zv[lane] = sv[lane];                             // 32 float4 = 128 floats
    if (lane < 16) zv[32 + lane] = sv[32 + lane];    // remaining 64 floats

    // ---- scalar outputs, distributed (all lanes hold the reduced values) ----
    if (lane < 5) {
        float rs, gs, bs, dsum;
        unpack2(p0, rs, gs);
        unpack2(p1, bs, dsum);
        if (lane < 3) {
            const float v = (lane == 0) ? rs : (lane == 1) ? gs : bs;
            rgb_out[(size_t)ray * 3 + lane] = v;
        } else if (lane == 3) {
            depth_out[ray] = __fdividef(dsum, wsum + 1e-8f);
        } else {
            acc_out[ray] = wsum;
        }
    }
}

extern "C" void kernel_launch(void* const* d_in, const int* in_sizes, int n_in,
                              void* d_out, int out_size)
{
    const float* near_   = (const float*)d_in[0];
    const float* far_    = (const float*)d_in[1];
    const float* density = (const float*)d_in[2];
    const float* rgb     = (const float*)d_in[3];
    const int B = in_sizes[0];

    float* out   = (float*)d_out;
    float* zs    = out;                       // B * 192
    float* rgbo  = zs + (size_t)B * NC;       // B * 3
    float* depth = rgbo + (size_t)B * 3;      // B
    float* acc   = depth + B;                 // B

    const int blocks = (B + WPB - 1) / WPB;
    pdf_sampler_kernel<<<blocks, WPB * 32>>>(near_, far_, density, rgb,
                                             zs, rgbo, depth, acc, B);
}